// round 2
// baseline (speedup 1.0000x reference)
#include <cuda_runtime.h>
#include <math.h>

#define Bb   2
#define Ss   2048
#define Hh   16
#define DH   64
#define Dd   1024
#define TOKENS (Bb*Ss)          // 4096

// ---------------- device scratch (no allocations allowed) ----------------
__device__ float g_Q[Bb*Ss*Dd];   // (B,S,H,DH) flattened == (4096,1024)
__device__ float g_K[Bb*Ss*Dd];
__device__ float g_V[Bb*Ss*Dd];
__device__ float g_P[Bb*Ss*Dd];   // preproj (B,S,H,DH)
__device__ int   g_bool_mode;     // 0 = uint8, 1 = int32, 2 = float32

// =====================================================================
// Detect how jnp.bool_ inputs were serialized. `mask` is all-True, so
// its first 32-bit word fingerprints the encoding:
//   0x00000001 -> int32 bools, 0x3F800000 -> float32, 0x01010101 -> uint8
// =====================================================================
__global__ void detect_bool_mode(const unsigned int* __restrict__ mask_raw)
{
    unsigned int w = mask_raw[0];
    int m = 0;
    if (w == 1u)           m = 1;
    else if (w == 0x3F800000u) m = 2;
    g_bool_mode = m;
}

__device__ __forceinline__ void load_bool4(const void* p, size_t idx, int mode,
                                           int r[4])
{
    if (mode == 1) {
        const int4 v = *(const int4*)((const int*)p + idx);
        r[0] = (v.x != 0); r[1] = (v.y != 0); r[2] = (v.z != 0); r[3] = (v.w != 0);
    } else if (mode == 2) {
        const float4 v = *(const float4*)((const float*)p + idx);
        r[0] = (v.x != 0.f); r[1] = (v.y != 0.f); r[2] = (v.z != 0.f); r[3] = (v.w != 0.f);
    } else {
        const uchar4 v = *(const uchar4*)((const unsigned char*)p + idx);
        r[0] = v.x; r[1] = v.y; r[2] = v.z; r[3] = v.w;
    }
}

// =====================================================================
// Classic SGEMM: C[M,N] = A[M,K] @ B[K,N] + bias[N]
// BM=BN=128, BK=8, 256 threads, 8x8 register tile per thread.
// =====================================================================
__global__ __launch_bounds__(256) void sgemm_bias(
    const float* __restrict__ A, const float* __restrict__ B,
    const float* __restrict__ bias, float* __restrict__ C,
    int M, int N, int K)
{
    __shared__ float As[8][128];
    __shared__ float Bs[8][128];

    const int tid = threadIdx.x;
    const int bm  = blockIdx.y * 128;
    const int bn  = blockIdx.x * 128;
    const int ty  = tid >> 4;          // 0..15
    const int tx  = tid & 15;          // 0..15

    const int arow = tid >> 1;          // 0..127
    const int acol = (tid & 1) * 4;     // 0 or 4
    const int brow = tid >> 5;          // 0..7
    const int bcol = (tid & 31) * 4;    // 0..124

    const float* Aptr = A + (size_t)(bm + arow) * K + acol;
    const float* Bptr = B + (size_t)brow * N + bn + bcol;

    float acc[8][8];
#pragma unroll
    for (int i = 0; i < 8; i++)
#pragma unroll
        for (int j = 0; j < 8; j++) acc[i][j] = 0.0f;

    for (int k0 = 0; k0 < K; k0 += 8) {
        float4 av = *(const float4*)(Aptr + k0);
        As[acol + 0][arow] = av.x;
        As[acol + 1][arow] = av.y;
        As[acol + 2][arow] = av.z;
        As[acol + 3][arow] = av.w;
        *(float4*)&Bs[brow][bcol] = *(const float4*)(Bptr + (size_t)k0 * N);
        __syncthreads();

#pragma unroll
        for (int k = 0; k < 8; k++) {
            float rm[8], rn[8];
            *(float4*)&rm[0] = *(float4*)&As[k][ty * 8];
            *(float4*)&rm[4] = *(float4*)&As[k][ty * 8 + 4];
            *(float4*)&rn[0] = *(float4*)&Bs[k][tx * 8];
            *(float4*)&rn[4] = *(float4*)&Bs[k][tx * 8 + 4];
#pragma unroll
            for (int i = 0; i < 8; i++)
#pragma unroll
                for (int j = 0; j < 8; j++)
                    acc[i][j] += rm[i] * rn[j];
        }
        __syncthreads();
    }

#pragma unroll
    for (int i = 0; i < 8; i++) {
        float* crow = C + (size_t)(bm + ty * 8 + i) * N + bn + tx * 8;
#pragma unroll
        for (int j = 0; j < 8; j++)
            crow[j] = acc[i][j] + bias[bn + tx * 8 + j];
    }
}

// =====================================================================
// Fused attention per (b, h, 16-query-row tile):
//   logits (dropout*scale + additive mask) -> smem row buffer (16x2048 f32)
//   exact softmax (exp computed once), weights -> gmem output region
//   P = W @ V -> g_P
// 256 threads. Dynamic smem = (16*2048 + 16*68 + 128*68) floats = 170,240 B.
// =====================================================================
#define KVP 68   // padded row stride (floats) for 64-wide K/V tiles
#define ATTN_SMEM ((16*2048 + 16*KVP + 128*KVP) * (int)sizeof(float))

__global__ __launch_bounds__(256) void attn_kernel(
    const void* __restrict__ mask,   // (B,1,S,S) bool (encoding per g_bool_mode)
    const void* __restrict__ drop,   // (B,H,S,S) bool
    float* __restrict__ attn_w)      // (B,H,S,S) f32
{
    extern __shared__ float sm[];
    float* Lg  = sm;                 // 16 x 2048 logits / exp / weights
    float* Qs  = Lg + 16 * 2048;     // 16 x KVP
    float* KVs = Qs + 16 * KVP;      // 128 x KVP

    const int b  = blockIdx.z;
    const int h  = blockIdx.y;
    const int q0 = blockIdx.x * 16;
    const int tid = threadIdx.x;
    const int mode = g_bool_mode;
    const float scale = 0.125f;      // 64^-0.5

    // ---- load Q tile (16 x 64) ----
    {
        const int r = tid >> 4, c = (tid & 15) * 4;
        *(float4*)&Qs[r * KVP + c] =
            *(const float4*)(g_Q + ((size_t)(b * Ss + q0 + r)) * Dd + h * DH + c);
    }

    // ---- logits: loop K tiles of 128 rows ----
    const int qg = tid >> 5;         // 0..7  -> q pair
    const int kg = tid & 31;         // 0..31 -> k quad
    const int q  = qg * 2;
    const int k  = kg * 4;

    for (int kt = 0; kt < Ss; kt += 128) {
        __syncthreads();             // protect previous KVs use
        for (int i = tid; i < 128 * 16; i += 256) {
            const int r = i >> 4, c = (i & 15) * 4;
            *(float4*)&KVs[r * KVP + c] =
                *(const float4*)(g_K + ((size_t)(b * Ss + kt + r)) * Dd + h * DH + c);
        }
        __syncthreads();

        float acc0[4] = {0.f, 0.f, 0.f, 0.f};
        float acc1[4] = {0.f, 0.f, 0.f, 0.f};
#pragma unroll
        for (int d = 0; d < 64; d += 4) {
            const float4 qa = *(const float4*)&Qs[q * KVP + d];
            const float4 qb = *(const float4*)&Qs[(q + 1) * KVP + d];
#pragma unroll
            for (int j = 0; j < 4; j++) {
                const float4 kv = *(const float4*)&KVs[(k + j) * KVP + d];
                acc0[j] += qa.x * kv.x + qa.y * kv.y + qa.z * kv.z + qa.w * kv.w;
                acc1[j] += qb.x * kv.x + qb.y * kv.y + qb.z * kv.z + qb.w * kv.w;
            }
        }

        // epilogue: dropout*scale + additive mask, store to smem row buffer
#pragma unroll
        for (int i = 0; i < 2; i++) {
            const int gq = q0 + q + i;
            int dm4[4], mk4[4];
            load_bool4(drop, ((size_t)(b * Hh + h) * Ss + gq) * Ss + kt + k, mode, dm4);
            load_bool4(mask, ((size_t)(b * Ss + gq)) * Ss + kt + k,          mode, mk4);
            float* lrow = &Lg[(q + i) * Ss + kt + k];
            const float* acc = i ? acc1 : acc0;
#pragma unroll
            for (int j = 0; j < 4; j++)
                lrow[j] = (dm4[j] ? acc[j] * scale : 0.f) + (mk4[j] ? 0.f : -1e9f);
        }
    }
    __syncthreads();

    // ---- softmax: one warp handles 2 rows ----
    {
        const int w = tid >> 5, lane = tid & 31;
#pragma unroll
        for (int rr = 0; rr < 2; rr++) {
            const int r = w * 2 + rr;
            float* lrow = &Lg[r * Ss];
            float m = -3.4e38f;
            for (int kk = lane; kk < Ss; kk += 32) m = fmaxf(m, lrow[kk]);
#pragma unroll
            for (int o = 16; o; o >>= 1) m = fmaxf(m, __shfl_xor_sync(0xffffffffu, m, o));
            float s = 0.f;
            for (int kk = lane; kk < Ss; kk += 32) {
                const float e = __expf(lrow[kk] - m);
                lrow[kk] = e;
                s += e;
            }
#pragma unroll
            for (int o = 16; o; o >>= 1) s += __shfl_xor_sync(0xffffffffu, s, o);
            const float inv = 1.0f / s;
            float* orow = attn_w + ((size_t)(b * Hh + h) * Ss + q0 + r) * Ss;
            for (int kk = lane; kk < Ss; kk += 32) {
                const float wv = lrow[kk] * inv;
                lrow[kk] = wv;        // keep for PV
                orow[kk] = wv;        // output attn_weights
            }
        }
    }
    __syncthreads();

    // ---- P = W @ V  (each thread: 1 q row, 4 output dims) ----
    {
        const int qq = tid >> 4;
        const int c  = (tid & 15) * 4;
        float4 acc = make_float4(0.f, 0.f, 0.f, 0.f);
        for (int kt = 0; kt < Ss; kt += 128) {
            __syncthreads();
            for (int i = tid; i < 128 * 16; i += 256) {
                const int r = i >> 4, cc = (i & 15) * 4;
                *(float4*)&KVs[r * KVP + cc] =
                    *(const float4*)(g_V + ((size_t)(b * Ss + kt + r)) * Dd + h * DH + cc);
            }
            __syncthreads();
            const float* lrow = &Lg[qq * Ss + kt];
#pragma unroll 8
            for (int kk = 0; kk < 128; kk++) {
                const float wv = lrow[kk];
                const float4 vv = *(const float4*)&KVs[kk * KVP + c];
                acc.x += wv * vv.x;
                acc.y += wv * vv.y;
                acc.z += wv * vv.z;
                acc.w += wv * vv.w;
            }
        }
        *(float4*)(g_P + ((size_t)(b * Ss + q0 + qq)) * Dd + h * DH + c) = acc;
    }
}

// =====================================================================
// launch
// =====================================================================
extern "C" void kernel_launch(void* const* d_in, const int* in_sizes, int n_in,
                              void* d_out, int out_size)
{
    const float* x_q  = (const float*)d_in[0];   // query_sequence (B,S,D)
    const float* x_kv = (const float*)d_in[1];   // kv_sequence    (B,S,D)
    const void*  mask = d_in[2];                 // (B,1,S,S) bool (enc unknown)
    const void*  drop = d_in[3];                 // (B,H,S,S) bool
    const float* wq = (const float*)d_in[4];
    const float* bq = (const float*)d_in[5];
    const float* wk = (const float*)d_in[6];
    const float* bk = (const float*)d_in[7];
    const float* wv = (const float*)d_in[8];
    const float* bv = (const float*)d_in[9];
    const float* wo = (const float*)d_in[10];
    const float* bo = (const float*)d_in[11];

    float* out    = (float*)d_out;                       // (B,S,D) first
    float* attn_w = out + (size_t)Bb * Ss * Dd;          // then (B,H,S,S)

    float *Qp, *Kp, *Vp, *Pp;
    cudaGetSymbolAddress((void**)&Qp, g_Q);
    cudaGetSymbolAddress((void**)&Kp, g_K);
    cudaGetSymbolAddress((void**)&Vp, g_V);
    cudaGetSymbolAddress((void**)&Pp, g_P);

    cudaFuncSetAttribute(attn_kernel,
                         cudaFuncAttributeMaxDynamicSharedMemorySize, ATTN_SMEM);

    detect_bool_mode<<<1, 1>>>((const unsigned int*)mask);

    const dim3 gg(Dd / 128, TOKENS / 128);   // (8, 32)
    // projections: X(4096,1024) @ W(1024,1024) + bias
    sgemm_bias<<<gg, 256>>>(x_q,  wq, bq, Qp, TOKENS, Dd, Dd);
    sgemm_bias<<<gg, 256>>>(x_kv, wk, bk, Kp, TOKENS, Dd, Dd);
    sgemm_bias<<<gg, 256>>>(x_kv, wv, bv, Vp, TOKENS, Dd, Dd);

    attn_kernel<<<dim3(Ss / 16, Hh, Bb), 256, ATTN_SMEM>>>(mask, drop, attn_w);

    // output projection: preproj(4096,1024) @ wo(1024,1024) + bo
    sgemm_bias<<<gg, 256>>>(Pp, wo, bo, out, TOKENS, Dd, Dd);
}

// round 3
// speedup vs baseline: 1.5732x; 1.5732x over previous
#include <cuda_runtime.h>
#include <cuda_bf16.h>
#include <math.h>

#define Bb   2
#define Ss   2048
#define Hh   16
#define DH   64
#define Dd   1024
#define TOKENS (Bb*Ss)          // 4096

// ---------------- device scratch (no allocations allowed) ----------------
__device__ float g_Q[Bb*Ss*Dd];   // (B,S,H,DH) flattened == (4096,1024)
__device__ float g_K[Bb*Ss*Dd];
__device__ float g_V[Bb*Ss*Dd];
__device__ float g_P[Bb*Ss*Dd];   // preproj (B,S,H,DH)
__device__ int   g_bool_mode;     // 0 = uint8, 1 = int32, 2 = float32

// =====================================================================
// bool-encoding fingerprint (mask is all-True by construction)
// =====================================================================
__global__ void detect_bool_mode(const unsigned int* __restrict__ mask_raw)
{
    unsigned int w = mask_raw[0];
    int m = 0;
    if (w == 1u)               m = 1;
    else if (w == 0x3F800000u) m = 2;
    g_bool_mode = m;
}

__device__ __forceinline__ void load_bool2(const void* p, size_t idx, int mode,
                                           int& f0, int& f1)
{
    if (mode == 1) {
        const int2 v = *(const int2*)((const int*)p + idx);
        f0 = (v.x != 0); f1 = (v.y != 0);
    } else if (mode == 2) {
        const float2 v = *(const float2*)((const float*)p + idx);
        f0 = (v.x != 0.f); f1 = (v.y != 0.f);
    } else {
        const unsigned char* q = (const unsigned char*)p + idx;
        f0 = q[0]; f1 = q[1];
    }
}

// =====================================================================
// bf16x3 machinery: fp32 -> packed (hi | lo<<16), fragments, mma
// =====================================================================
__device__ __forceinline__ unsigned pack_split(float a)
{
    __nv_bfloat16 h = __float2bfloat16(a);
    float r = a - __bfloat162float(h);
    __nv_bfloat16 l = __float2bfloat16(r);
    return (unsigned)__bfloat16_as_ushort(h) |
           ((unsigned)__bfloat16_as_ushort(l) << 16);
}

struct FragA { unsigned hi[4], lo[4]; };
struct FragB { unsigned hi[2], lo[2]; };

// A fragment (m16 x k16) from packed row-major [m][k] tile
__device__ __forceinline__ void ldA(const unsigned* S, int pitch, int mr, int kc,
                                    int g, int t, FragA& f)
{
    const unsigned* p0 = S + (size_t)(mr + g) * pitch + kc + 2 * t;
    const unsigned* p1 = S + (size_t)(mr + g + 8) * pitch + kc + 2 * t;
    unsigned w0 = p0[0], w1 = p0[1], w2 = p0[8], w3 = p0[9];
    unsigned v0 = p1[0], v1 = p1[1], v2 = p1[8], v3 = p1[9];
    f.hi[0] = __byte_perm(w0, w1, 0x5410); f.lo[0] = __byte_perm(w0, w1, 0x7632);
    f.hi[1] = __byte_perm(v0, v1, 0x5410); f.lo[1] = __byte_perm(v0, v1, 0x7632);
    f.hi[2] = __byte_perm(w2, w3, 0x5410); f.lo[2] = __byte_perm(w2, w3, 0x7632);
    f.hi[3] = __byte_perm(v2, v3, 0x5410); f.lo[3] = __byte_perm(v2, v3, 0x7632);
}

// B fragment (k16 x n8) from packed [n][k] tile
__device__ __forceinline__ void ldB(const unsigned* S, int pitch, int nb, int kc,
                                    int g, int t, FragB& f)
{
    const unsigned* p = S + (size_t)(nb + g) * pitch + kc + 2 * t;
    unsigned u0 = p[0], u1 = p[1], u2 = p[8], u3 = p[9];
    f.hi[0] = __byte_perm(u0, u1, 0x5410); f.lo[0] = __byte_perm(u0, u1, 0x7632);
    f.hi[1] = __byte_perm(u2, u3, 0x5410); f.lo[1] = __byte_perm(u2, u3, 0x7632);
}

__device__ __forceinline__ void mma16816(float c[4],
    unsigned a0, unsigned a1, unsigned a2, unsigned a3, unsigned b0, unsigned b1)
{
    asm volatile(
        "mma.sync.aligned.m16n8k16.row.col.f32.bf16.bf16.f32 "
        "{%0,%1,%2,%3}, {%4,%5,%6,%7}, {%8,%9}, {%0,%1,%2,%3};\n"
        : "+f"(c[0]), "+f"(c[1]), "+f"(c[2]), "+f"(c[3])
        : "r"(a0), "r"(a1), "r"(a2), "r"(a3), "r"(b0), "r"(b1));
}

__device__ __forceinline__ void mma3(float c[4], const FragA& a, const FragB& b)
{
    mma16816(c, a.hi[0], a.hi[1], a.hi[2], a.hi[3], b.hi[0], b.hi[1]);
    mma16816(c, a.hi[0], a.hi[1], a.hi[2], a.hi[3], b.lo[0], b.lo[1]);
    mma16816(c, a.lo[0], a.lo[1], a.lo[2], a.lo[3], b.hi[0], b.hi[1]);
}

// =====================================================================
// Tensor-core GEMM (bf16x3): C[M,N] = A[M,K] @ B[K,N] + bias
// BM=BN=128, BK=32, 256 threads = 8 warps (2x4), warp tile 64x32.
// =====================================================================
#define GP 36
__global__ __launch_bounds__(256) void gemm3_bias(
    const float* __restrict__ A, const float* __restrict__ B,
    const float* __restrict__ bias, float* __restrict__ C,
    int M, int N, int K)
{
    __shared__ unsigned SA[128 * GP];
    __shared__ unsigned SB[128 * GP];

    const int tid = threadIdx.x;
    const int lane = tid & 31, wid = tid >> 5;
    const int g = lane >> 2, t = lane & 3;
    const int bm = blockIdx.y * 128, bn = blockIdx.x * 128;
    const int wm = (wid >> 2) * 64, wn = (wid & 3) * 32;

    float acc[4][4][4];
#pragma unroll
    for (int i = 0; i < 4; i++)
#pragma unroll
        for (int j = 0; j < 4; j++)
#pragma unroll
            for (int r = 0; r < 4; r++) acc[i][j][r] = 0.f;

    for (int k0 = 0; k0 < K; k0 += 32) {
        __syncthreads();
#pragma unroll
        for (int it = 0; it < 16; it++) {
            int idx = it * 256 + tid;
            int r = idx >> 5, c = idx & 31;
            SA[r * GP + c] = pack_split(A[(size_t)(bm + r) * K + k0 + c]);
        }
#pragma unroll
        for (int it = 0; it < 16; it++) {
            int idx = it * 256 + tid;
            int n = idx & 127, k = idx >> 7;
            SB[n * GP + k] = pack_split(B[(size_t)(k0 + k) * N + bn + n]);
        }
        __syncthreads();

#pragma unroll
        for (int ks = 0; ks < 2; ks++) {
            FragB fb[4];
#pragma unroll
            for (int nt = 0; nt < 4; nt++)
                ldB(SB, GP, wn + nt * 8, ks * 16, g, t, fb[nt]);
#pragma unroll
            for (int mt = 0; mt < 4; mt++) {
                FragA fa;
                ldA(SA, GP, wm + mt * 16, ks * 16, g, t, fa);
#pragma unroll
                for (int nt = 0; nt < 4; nt++)
                    mma3(acc[mt][nt], fa, fb[nt]);
            }
        }
    }

#pragma unroll
    for (int mt = 0; mt < 4; mt++) {
#pragma unroll
        for (int nt = 0; nt < 4; nt++) {
            const int row = bm + wm + mt * 16 + g;
            const int col = bn + wn + nt * 8 + 2 * t;
            const float2 bb = *(const float2*)(bias + col);
            float* cp = C + (size_t)row * N + col;
            float2 r0 = make_float2(acc[mt][nt][0] + bb.x, acc[mt][nt][1] + bb.y);
            float2 r1 = make_float2(acc[mt][nt][2] + bb.x, acc[mt][nt][3] + bb.y);
            *(float2*)cp = r0;
            *(float2*)(cp + (size_t)8 * N) = r1;
        }
    }
}

// =====================================================================
// Fused attention with bf16x3 mma:
//  per block: (b, h, 16 q-rows). logits -> smem fp32 (pitch LP),
//  dropout*scale + mask epilogue, softmax (writes attn_w, repacks
//  weights in place as bf16 hi/lo), PV via mma -> g_P.
// =====================================================================
#define LP 2052
#define QPITCH 68
#define KPITCH 68
#define VPITCH 132
#define ATTN_WORDS (16*LP + 16*QPITCH + 128*KPITCH)
#define ATTN_SMEM (ATTN_WORDS * (int)sizeof(unsigned))

__global__ __launch_bounds__(256) void attn_mma(
    const void* __restrict__ mask,   // (B,1,S,S)
    const void* __restrict__ drop,   // (B,H,S,S)
    float* __restrict__ attn_w)      // (B,H,S,S)
{
    extern __shared__ unsigned sm[];
    unsigned* Lg = sm;                     // 16 x LP (fp32 then packed bf16)
    unsigned* Qp = Lg + 16 * LP;           // 16 x QPITCH packed
    unsigned* KV = Qp + 16 * QPITCH;       // K: 128xKPITCH / V^T: 64xVPITCH
    float* Lf = (float*)Lg;

    const int b = blockIdx.z, h = blockIdx.y, q0 = blockIdx.x * 16;
    const int tid = threadIdx.x;
    const int lane = tid & 31, wid = tid >> 5;
    const int g = lane >> 2, t = lane & 3;
    const int mode = g_bool_mode;

    // ---- Q tile (16 x 64) split+pack ----
#pragma unroll
    for (int it = 0; it < 4; it++) {
        int idx = it * 256 + tid;
        int r = idx >> 6, c = idx & 63;
        Qp[r * QPITCH + c] =
            pack_split(g_Q[(size_t)(b * Ss + q0 + r) * Dd + h * DH + c]);
    }

    // ---- logits ----
    const size_t drow = (size_t)(b * Hh + h) * Ss;
    const size_t mrow = (size_t)b * Ss;
    for (int kt = 0; kt < Ss; kt += 128) {
        __syncthreads();
#pragma unroll
        for (int it = 0; it < 32; it++) {
            int idx = it * 256 + tid;
            int r = idx >> 6, c = idx & 63;
            KV[r * KPITCH + c] =
                pack_split(g_K[(size_t)(b * Ss + kt + r) * Dd + h * DH + c]);
        }
        __syncthreads();

        float c0[4] = {0.f, 0.f, 0.f, 0.f};
        float c1[4] = {0.f, 0.f, 0.f, 0.f};
        const int nb = wid * 16;
#pragma unroll
        for (int ks = 0; ks < 4; ks++) {
            FragA fa;
            ldA(Qp, QPITCH, 0, ks * 16, g, t, fa);
            FragB fb0, fb1;
            ldB(KV, KPITCH, nb,     ks * 16, g, t, fb0);
            ldB(KV, KPITCH, nb + 8, ks * 16, g, t, fb1);
            mma3(c0, fa, fb0);
            mma3(c1, fa, fb1);
        }

        // epilogue: dropout*scale + additive mask -> Lf
#pragma unroll
        for (int nt = 0; nt < 2; nt++) {
            const float* c = nt ? c1 : c0;
            const int col = kt + nb + nt * 8 + 2 * t;   // global k col (even)
#pragma unroll
            for (int half = 0; half < 2; half++) {
                const int row = g + half * 8;
                const int gq = q0 + row;
                int d0, d1, m0, m1;
                load_bool2(drop, (drow + gq) * Ss + col, mode, d0, d1);
                load_bool2(mask, (mrow + gq) * Ss + col, mode, m0, m1);
                float l0 = (d0 ? c[half * 2 + 0] * 0.125f : 0.f) + (m0 ? 0.f : -1e9f);
                float l1 = (d1 ? c[half * 2 + 1] * 0.125f : 0.f) + (m1 ? 0.f : -1e9f);
                Lf[row * LP + col]     = l0;
                Lf[row * LP + col + 1] = l1;
            }
        }
    }
    __syncthreads();

    // ---- softmax (2 rows per warp), write attn_w, repack weights in place ----
    {
#pragma unroll
        for (int rr = 0; rr < 2; rr++) {
            const int r = wid * 2 + rr;
            float* lrow = Lf + r * LP;
            float m = -3.4e38f;
            for (int kk = lane; kk < Ss; kk += 32) m = fmaxf(m, lrow[kk]);
#pragma unroll
            for (int o = 16; o; o >>= 1) m = fmaxf(m, __shfl_xor_sync(0xffffffffu, m, o));
            float s = 0.f;
            for (int kk = lane; kk < Ss; kk += 32) {
                const float e = __expf(lrow[kk] - m);
                lrow[kk] = e;
                s += e;
            }
#pragma unroll
            for (int o = 16; o; o >>= 1) s += __shfl_xor_sync(0xffffffffu, s, o);
            const float inv = 1.0f / s;
            float* orow = attn_w + ((size_t)(b * Hh + h) * Ss + q0 + r) * Ss;
            unsigned* prow = Lg + r * LP;
            for (int kk = lane; kk < Ss; kk += 32) {
                const float wv = lrow[kk] * inv;
                orow[kk] = wv;
                prow[kk] = pack_split(wv);
            }
        }
    }

    // ---- PV: D(16 x 64) = W(16 x 2048) @ V(2048 x 64) ----
    float d[4] = {0.f, 0.f, 0.f, 0.f};
    const int nb = wid * 8;   // d-dim strip for this warp
    for (int kt = 0; kt < Ss; kt += 128) {
        __syncthreads();
#pragma unroll
        for (int it = 0; it < 32; it++) {
            int idx = it * 256 + tid;
            int r = idx >> 6, c = idx & 63;   // r = token, c = d
            KV[c * VPITCH + r] =
                pack_split(g_V[(size_t)(b * Ss + kt + r) * Dd + h * DH + c]);
        }
        __syncthreads();

#pragma unroll
        for (int ks = 0; ks < 8; ks++) {
            FragA fa;
            ldA(Lg, LP, 0, kt + ks * 16, g, t, fa);
            FragB fb;
            ldB(KV, VPITCH, nb, ks * 16, g, t, fb);
            mma3(d, fa, fb);
        }
    }

    {
        float* pr = g_P + (size_t)(b * Ss + q0 + g) * Dd + h * DH + nb + 2 * t;
        *(float2*)pr = make_float2(d[0], d[1]);
        *(float2*)(pr + (size_t)8 * Dd) = make_float2(d[2], d[3]);
    }
}

// =====================================================================
// launch
// =====================================================================
extern "C" void kernel_launch(void* const* d_in, const int* in_sizes, int n_in,
                              void* d_out, int out_size)
{
    const float* x_q  = (const float*)d_in[0];
    const float* x_kv = (const float*)d_in[1];
    const void*  mask = d_in[2];
    const void*  drop = d_in[3];
    const float* wq = (const float*)d_in[4];
    const float* bq = (const float*)d_in[5];
    const float* wk = (const float*)d_in[6];
    const float* bk = (const float*)d_in[7];
    const float* wv = (const float*)d_in[8];
    const float* bv = (const float*)d_in[9];
    const float* wo = (const float*)d_in[10];
    const float* bo = (const float*)d_in[11];

    float* out    = (float*)d_out;
    float* attn_w = out + (size_t)Bb * Ss * Dd;

    float *Qp_, *Kp_, *Vp_, *Pp_;
    cudaGetSymbolAddress((void**)&Qp_, g_Q);
    cudaGetSymbolAddress((void**)&Kp_, g_K);
    cudaGetSymbolAddress((void**)&Vp_, g_V);
    cudaGetSymbolAddress((void**)&Pp_, g_P);

    cudaFuncSetAttribute(attn_mma,
                         cudaFuncAttributeMaxDynamicSharedMemorySize, ATTN_SMEM);

    detect_bool_mode<<<1, 1>>>((const unsigned int*)mask);

    const dim3 gg(Dd / 128, TOKENS / 128);   // (8, 32)
    gemm3_bias<<<gg, 256>>>(x_q,  wq, bq, Qp_, TOKENS, Dd, Dd);
    gemm3_bias<<<gg, 256>>>(x_kv, wk, bk, Kp_, TOKENS, Dd, Dd);
    gemm3_bias<<<gg, 256>>>(x_kv, wv, bv, Vp_, TOKENS, Dd, Dd);

    attn_mma<<<dim3(Ss / 16, Hh, Bb), 256, ATTN_SMEM>>>(mask, drop, attn_w);

    gemm3_bias<<<gg, 256>>>(Pp_, wo, bo, out, TOKENS, Dd, Dd);
}

// round 5
// speedup vs baseline: 3.7917x; 2.4102x over previous
#include <cuda_runtime.h>
#include <cuda_bf16.h>
#include <math.h>

#define Bb   2
#define Ss   2048
#define Hh   16
#define DH   64
#define Dd   1024
#define TOKENS (Bb*Ss)          // 4096

// ---------------- device scratch (no allocations allowed) ----------------
__device__ unsigned g_Xq [TOKENS*Dd];   // packed inputs
__device__ unsigned g_Xkv[TOKENS*Dd];
__device__ unsigned g_Wq [Dd*Dd];       // packed transposed weights [n][k]
__device__ unsigned g_Wk [Dd*Dd];
__device__ unsigned g_Wv [Dd*Dd];
__device__ unsigned g_Wo [Dd*Dd];
__device__ unsigned g_Qp [TOKENS*Dd];   // packed Q (pre-scaled), K, V, P
__device__ unsigned g_Kp [TOKENS*Dd];
__device__ unsigned g_Vp [TOKENS*Dd];
__device__ unsigned g_Pp [TOKENS*Dd];
__device__ int      g_bool_mode;        // 0 = uint8, 1 = int32, 2 = float32

// =====================================================================
// bool-encoding fingerprint (mask is all-True by construction)
// =====================================================================
__global__ void detect_bool_mode(const unsigned int* __restrict__ mask_raw)
{
    unsigned int w = mask_raw[0];
    int m = 0;
    if (w == 1u)               m = 1;
    else if (w == 0x3F800000u) m = 2;
    g_bool_mode = m;
}

__device__ __forceinline__ void load_bool2(const void* p, size_t idx, int mode,
                                           int& f0, int& f1)
{
    if (mode == 1) {
        const int2 v = *(const int2*)((const int*)p + idx);
        f0 = (v.x != 0); f1 = (v.y != 0);
    } else if (mode == 2) {
        const float2 v = *(const float2*)((const float*)p + idx);
        f0 = (v.x != 0.f); f1 = (v.y != 0.f);
    } else {
        const unsigned char* q = (const unsigned char*)p + idx;
        f0 = q[0]; f1 = q[1];
    }
}

// =====================================================================
// bf16x3: fp32 -> packed (hi | lo<<16), fragment loads, mma
// =====================================================================
__device__ __forceinline__ unsigned pack_split(float a)
{
    __nv_bfloat16 h = __float2bfloat16(a);
    float r = a - __bfloat162float(h);
    __nv_bfloat16 l = __float2bfloat16(r);
    return (unsigned)__bfloat16_as_ushort(h) |
           ((unsigned)__bfloat16_as_ushort(l) << 16);
}

struct FragA { unsigned hi[4], lo[4]; };
struct FragB { unsigned hi[2], lo[2]; };

__device__ __forceinline__ void ldA(const unsigned* S, int pitch, int mr, int kc,
                                    int g, int t, FragA& f)
{
    const unsigned* p0 = S + (size_t)(mr + g) * pitch + kc + 2 * t;
    const unsigned* p1 = S + (size_t)(mr + g + 8) * pitch + kc + 2 * t;
    unsigned w0 = p0[0], w1 = p0[1], w2 = p0[8], w3 = p0[9];
    unsigned v0 = p1[0], v1 = p1[1], v2 = p1[8], v3 = p1[9];
    f.hi[0] = __byte_perm(w0, w1, 0x5410); f.lo[0] = __byte_perm(w0, w1, 0x7632);
    f.hi[1] = __byte_perm(v0, v1, 0x5410); f.lo[1] = __byte_perm(v0, v1, 0x7632);
    f.hi[2] = __byte_perm(w2, w3, 0x5410); f.lo[2] = __byte_perm(w2, w3, 0x7632);
    f.hi[3] = __byte_perm(v2, v3, 0x5410); f.lo[3] = __byte_perm(v2, v3, 0x7632);
}

__device__ __forceinline__ void ldB(const unsigned* S, int pitch, int nb, int kc,
                                    int g, int t, FragB& f)
{
    const unsigned* p = S + (size_t)(nb + g) * pitch + kc + 2 * t;
    unsigned u0 = p[0], u1 = p[1], u2 = p[8], u3 = p[9];
    f.hi[0] = __byte_perm(u0, u1, 0x5410); f.lo[0] = __byte_perm(u0, u1, 0x7632);
    f.hi[1] = __byte_perm(u2, u3, 0x5410); f.lo[1] = __byte_perm(u2, u3, 0x7632);
}

__device__ __forceinline__ void mma16816(float c[4],
    unsigned a0, unsigned a1, unsigned a2, unsigned a3, unsigned b0, unsigned b1)
{
    asm volatile(
        "mma.sync.aligned.m16n8k16.row.col.f32.bf16.bf16.f32 "
        "{%0,%1,%2,%3}, {%4,%5,%6,%7}, {%8,%9}, {%0,%1,%2,%3};\n"
        : "+f"(c[0]), "+f"(c[1]), "+f"(c[2]), "+f"(c[3])
        : "r"(a0), "r"(a1), "r"(a2), "r"(a3), "r"(b0), "r"(b1));
}

__device__ __forceinline__ void mma3(float c[4], const FragA& a, const FragB& b)
{
    mma16816(c, a.hi[0], a.hi[1], a.hi[2], a.hi[3], b.hi[0], b.hi[1]);
    mma16816(c, a.hi[0], a.hi[1], a.hi[2], a.hi[3], b.lo[0], b.lo[1]);
    mma16816(c, a.lo[0], a.lo[1], a.lo[2], a.lo[3], b.hi[0], b.hi[1]);
}

// =====================================================================
// pack helpers
// =====================================================================
__global__ __launch_bounds__(256) void pack_arr(const float* __restrict__ src,
                                                unsigned* __restrict__ dst, int n)
{
    for (int i = blockIdx.x * 256 + threadIdx.x; i < n; i += gridDim.x * 256)
        dst[i] = pack_split(src[i]);
}

// W[K][N] row-major -> out[n*K + k] packed (transpose)
__global__ __launch_bounds__(256) void pack_wT(const float* __restrict__ W,
                                               unsigned* __restrict__ out,
                                               int K, int N)
{
    __shared__ float t[32][33];
    const int k0 = blockIdx.y * 32, n0 = blockIdx.x * 32;
    const int tx = threadIdx.x & 31, ty = threadIdx.x >> 5;   // 32 x 8
#pragma unroll
    for (int r = 0; r < 4; r++)
        t[ty + r * 8][tx] = W[(size_t)(k0 + ty + r * 8) * N + n0 + tx];
    __syncthreads();
#pragma unroll
    for (int r = 0; r < 4; r++)
        out[(size_t)(n0 + ty + r * 8) * K + k0 + tx] = pack_split(t[tx][ty + r * 8]);
}

// =====================================================================
// GEMM (bf16x3, pre-packed operands, cp.async double buffer):
//   C[M,N] = A[M,K] @ B^T   (A packed [M][K], B packed [N][K])
// BM=BN=128, BK=32, 256 threads = 8 warps (2x4), warp tile 64x32.
// PACKOUT=1: C = pack((acc + bias[n]) * scale)   (uint32)
// PACKOUT=0: C = acc + bias[n]                   (fp32)
// =====================================================================
#define GP 36
#define GBUF (128 * GP)

template<int PACKOUT>
__global__ __launch_bounds__(256) void gemm_bf3(
    const unsigned* __restrict__ A, const unsigned* __restrict__ B,
    const float* __restrict__ bias, float scale,
    unsigned* __restrict__ Cp, float* __restrict__ Cf,
    int M, int N, int K)
{
    extern __shared__ unsigned gsm[];

    const int tid = threadIdx.x;
    const int lane = tid & 31, wid = tid >> 5;
    const int g = lane >> 2, t = lane & 3;
    const int bm = blockIdx.y * 128, bn = blockIdx.x * 128;
    const int wm = (wid >> 2) * 64, wn = (wid & 3) * 32;

    float acc[4][4][4];
#pragma unroll
    for (int i = 0; i < 4; i++)
#pragma unroll
        for (int j = 0; j < 4; j++)
#pragma unroll
            for (int r = 0; r < 4; r++) acc[i][j][r] = 0.f;

    const int NC = K >> 5;

    auto ld_stage = [&](int st, int k0) {
        unsigned* SA = gsm + st * 2 * GBUF;
        unsigned* SB = SA + GBUF;
        // 128 rows x 32 words per tile; 16B per cp.async -> 1024 copies each
        // over 256 threads = 4 iterations (it<4; was it<8 = OOB bug in R4)
#pragma unroll
        for (int it = 0; it < 4; it++) {
            int idx = it * 256 + tid;
            int r = idx >> 3, q = (idx & 7) * 4;
            unsigned sa = (unsigned)__cvta_generic_to_shared(&SA[r * GP + q]);
            asm volatile("cp.async.cg.shared.global [%0], [%1], 16;\n"
                         :: "r"(sa), "l"(A + (size_t)(bm + r) * K + k0 + q) : "memory");
            unsigned sb = (unsigned)__cvta_generic_to_shared(&SB[r * GP + q]);
            asm volatile("cp.async.cg.shared.global [%0], [%1], 16;\n"
                         :: "r"(sb), "l"(B + (size_t)(bn + r) * K + k0 + q) : "memory");
        }
        asm volatile("cp.async.commit_group;\n" ::: "memory");
    };

    ld_stage(0, 0);
    for (int c = 0; c < NC; c++) {
        asm volatile("cp.async.wait_group 0;\n" ::: "memory");
        __syncthreads();
        if (c + 1 < NC) ld_stage((c + 1) & 1, (c + 1) * 32);

        unsigned* SA = gsm + (c & 1) * 2 * GBUF;
        unsigned* SB = SA + GBUF;
#pragma unroll
        for (int ks = 0; ks < 2; ks++) {
            FragB fb[4];
#pragma unroll
            for (int nt = 0; nt < 4; nt++)
                ldB(SB, GP, wn + nt * 8, ks * 16, g, t, fb[nt]);
#pragma unroll
            for (int mt = 0; mt < 4; mt++) {
                FragA fa;
                ldA(SA, GP, wm + mt * 16, ks * 16, g, t, fa);
#pragma unroll
                for (int nt = 0; nt < 4; nt++)
                    mma3(acc[mt][nt], fa, fb[nt]);
            }
        }
        __syncthreads();
    }

#pragma unroll
    for (int mt = 0; mt < 4; mt++) {
#pragma unroll
        for (int nt = 0; nt < 4; nt++) {
            const int col = bn + wn + nt * 8 + 2 * t;
            const float2 bb = *(const float2*)(bias + col);
#pragma unroll
            for (int half = 0; half < 2; half++) {
                const int row = bm + wm + mt * 16 + g + half * 8;
                const float v0 = acc[mt][nt][half * 2 + 0] + bb.x;
                const float v1 = acc[mt][nt][half * 2 + 1] + bb.y;
                if (PACKOUT) {
                    uint2 pv = make_uint2(pack_split(v0 * scale),
                                          pack_split(v1 * scale));
                    *(uint2*)(Cp + (size_t)row * N + col) = pv;
                } else {
                    *(float2*)(Cf + (size_t)row * N + col) = make_float2(v0, v1);
                }
            }
        }
    }
}

// =====================================================================
// Pass 1: logits = Qs @ K^T per (b,h), 128x128 blocks.
// Epilogue: dropout (pre-softmax) + additive mask, raw logits -> attn_w.
// Grid (Hh, 256, Bb): x fastest so 16 heads reuse the mask tile in L2.
// =====================================================================
#define AP 68
#define ALOG_SMEM (2 * 128 * AP * (int)sizeof(unsigned))

__global__ __launch_bounds__(256) void attn_logits(
    const void* __restrict__ mask, const void* __restrict__ drop,
    float* __restrict__ attn_w)
{
    extern __shared__ unsigned asm_[];
    unsigned* SQ = asm_;
    unsigned* SK = asm_ + 128 * AP;

    const int h = blockIdx.x, b = blockIdx.z;
    const int m0 = (blockIdx.y >> 4) * 128;
    const int n0 = (blockIdx.y & 15) * 128;
    const int tid = threadIdx.x;
    const int lane = tid & 31, wid = tid >> 5;
    const int g = lane >> 2, t = lane & 3;
    const int wm = (wid >> 2) * 64, wn = (wid & 3) * 32;
    const int mode = g_bool_mode;

#pragma unroll
    for (int it = 0; it < 8; it++) {
        int idx = it * 256 + tid;
        int r = idx >> 4, q = (idx & 15) * 4;
        *(uint4*)&SQ[r * AP + q] =
            *(const uint4*)(g_Qp + (size_t)(b * Ss + m0 + r) * Dd + h * DH + q);
        *(uint4*)&SK[r * AP + q] =
            *(const uint4*)(g_Kp + (size_t)(b * Ss + n0 + r) * Dd + h * DH + q);
    }
    __syncthreads();

    float acc[4][4][4];
#pragma unroll
    for (int i = 0; i < 4; i++)
#pragma unroll
        for (int j = 0; j < 4; j++)
#pragma unroll
            for (int r = 0; r < 4; r++) acc[i][j][r] = 0.f;

#pragma unroll
    for (int ks = 0; ks < 4; ks++) {
        FragB fb[4];
#pragma unroll
        for (int nt = 0; nt < 4; nt++)
            ldB(SK, AP, wn + nt * 8, ks * 16, g, t, fb[nt]);
#pragma unroll
        for (int mt = 0; mt < 4; mt++) {
            FragA fa;
            ldA(SQ, AP, wm + mt * 16, ks * 16, g, t, fa);
#pragma unroll
            for (int nt = 0; nt < 4; nt++)
                mma3(acc[mt][nt], fa, fb[nt]);
        }
    }

    const size_t drow = (size_t)(b * Hh + h) * Ss;
    const size_t mrow = (size_t)b * Ss;
#pragma unroll
    for (int mt = 0; mt < 4; mt++) {
#pragma unroll
        for (int nt = 0; nt < 4; nt++) {
            const int col = n0 + wn + nt * 8 + 2 * t;
#pragma unroll
            for (int half = 0; half < 2; half++) {
                const int gq = m0 + wm + mt * 16 + g + half * 8;
                int d0, d1, mk0, mk1;
                load_bool2(drop, (drow + gq) * Ss + col, mode, d0, d1);
                load_bool2(mask, (mrow + gq) * Ss + col, mode, mk0, mk1);
                const float l0 = (d0 ? acc[mt][nt][half * 2 + 0] : 0.f)
                                 + (mk0 ? 0.f : -1e9f);
                const float l1 = (d1 ? acc[mt][nt][half * 2 + 1] : 0.f)
                                 + (mk1 ? 0.f : -1e9f);
                *(float2*)(attn_w + (drow + gq) * Ss + col) = make_float2(l0, l1);
            }
        }
    }
}

// =====================================================================
// Pass 2: row softmax in place. One warp per row (row in registers).
// =====================================================================
__global__ __launch_bounds__(256) void softmax_rows(float* __restrict__ W)
{
    const int row = blockIdx.x * 8 + (threadIdx.x >> 5);
    const int lane = threadIdx.x & 31;
    float* base = W + (size_t)row * Ss;

    float4 v[16];
    float m = -3.4e38f;
#pragma unroll
    for (int i = 0; i < 16; i++) {
        v[i] = *(float4*)(base + i * 128 + lane * 4);
        m = fmaxf(m, fmaxf(fmaxf(v[i].x, v[i].y), fmaxf(v[i].z, v[i].w)));
    }
#pragma unroll
    for (int o = 16; o; o >>= 1) m = fmaxf(m, __shfl_xor_sync(0xffffffffu, m, o));

    float s = 0.f;
#pragma unroll
    for (int i = 0; i < 16; i++) {
        v[i].x = __expf(v[i].x - m); v[i].y = __expf(v[i].y - m);
        v[i].z = __expf(v[i].z - m); v[i].w = __expf(v[i].w - m);
        s += v[i].x + v[i].y + v[i].z + v[i].w;
    }
#pragma unroll
    for (int o = 16; o; o >>= 1) s += __shfl_xor_sync(0xffffffffu, s, o);
    const float inv = 1.0f / s;

#pragma unroll
    for (int i = 0; i < 16; i++) {
        v[i].x *= inv; v[i].y *= inv; v[i].z *= inv; v[i].w *= inv;
        *(float4*)(base + i * 128 + lane * 4) = v[i];
    }
}

// =====================================================================
// Pass 3: P = W @ V per (b,h). Block = 128 q rows x 64 d. K-loop over S.
// W read fp32 from attn_w (packed once here), V pre-packed.
// 8 warps 4x2, warp tile 32x32. Output packed -> g_Pp.
// =====================================================================
#define PVP 36
__global__ __launch_bounds__(256) void attn_pv(
    const float* __restrict__ attn_w)
{
    __shared__ unsigned SW[128 * PVP];
    __shared__ unsigned SV[64 * PVP];

    const int h = blockIdx.x, b = blockIdx.z;
    const int m0 = blockIdx.y * 128;
    const int tid = threadIdx.x;
    const int lane = tid & 31, wid = tid >> 5;
    const int g = lane >> 2, t = lane & 3;
    const int wm = (wid >> 1) * 32, wn = (wid & 1) * 32;
    const size_t wrow = (size_t)(b * Hh + h) * Ss;

    float acc[2][4][4];
#pragma unroll
    for (int i = 0; i < 2; i++)
#pragma unroll
        for (int j = 0; j < 4; j++)
#pragma unroll
            for (int r = 0; r < 4; r++) acc[i][j][r] = 0.f;

    for (int kc = 0; kc < Ss; kc += 32) {
        __syncthreads();
        // W tile 128 x 32 fp32 -> packed
#pragma unroll
        for (int it = 0; it < 4; it++) {
            int idx = it * 256 + tid;
            int r = idx >> 3, f4 = (idx & 7) * 4;
            float4 w4 = *(const float4*)(attn_w + (wrow + m0 + r) * Ss + kc + f4);
            SW[r * PVP + f4 + 0] = pack_split(w4.x);
            SW[r * PVP + f4 + 1] = pack_split(w4.y);
            SW[r * PVP + f4 + 2] = pack_split(w4.z);
            SW[r * PVP + f4 + 3] = pack_split(w4.w);
        }
        // V tile 32 tokens x 64 d -> smem [d][token]
#pragma unroll
        for (int it = 0; it < 2; it++) {
            int idx = it * 256 + tid;
            int tok = idx >> 4, d4 = (idx & 15) * 4;
            uint4 vv = *(const uint4*)(g_Vp + (size_t)(b * Ss + kc + tok) * Dd
                                       + h * DH + d4);
            SV[(d4 + 0) * PVP + tok] = vv.x;
            SV[(d4 + 1) * PVP + tok] = vv.y;
            SV[(d4 + 2) * PVP + tok] = vv.z;
            SV[(d4 + 3) * PVP + tok] = vv.w;
        }
        __syncthreads();

#pragma unroll
        for (int ks = 0; ks < 2; ks++) {
            FragB fb[4];
#pragma unroll
            for (int nt = 0; nt < 4; nt++)
                ldB(SV, PVP, wn + nt * 8, ks * 16, g, t, fb[nt]);
#pragma unroll
            for (int mt = 0; mt < 2; mt++) {
                FragA fa;
                ldA(SW, PVP, wm + mt * 16, ks * 16, g, t, fa);
#pragma unroll
                for (int nt = 0; nt < 4; nt++)
                    mma3(acc[mt][nt], fa, fb[nt]);
            }
        }
    }

#pragma unroll
    for (int mt = 0; mt < 2; mt++) {
#pragma unroll
        for (int nt = 0; nt < 4; nt++) {
            const int dh = wn + nt * 8 + 2 * t;
#pragma unroll
            for (int half = 0; half < 2; half++) {
                const int row = m0 + wm + mt * 16 + g + half * 8;
                uint2 pv = make_uint2(pack_split(acc[mt][nt][half * 2 + 0]),
                                      pack_split(acc[mt][nt][half * 2 + 1]));
                *(uint2*)(g_Pp + (size_t)(b * Ss + row) * Dd + h * DH + dh) = pv;
            }
        }
    }
}

// =====================================================================
// launch
// =====================================================================
#define GEMM_SMEM (4 * GBUF * (int)sizeof(unsigned))

extern "C" void kernel_launch(void* const* d_in, const int* in_sizes, int n_in,
                              void* d_out, int out_size)
{
    const float* x_q  = (const float*)d_in[0];
    const float* x_kv = (const float*)d_in[1];
    const void*  mask = d_in[2];
    const void*  drop = d_in[3];
    const float* wq = (const float*)d_in[4];
    const float* bq = (const float*)d_in[5];
    const float* wk = (const float*)d_in[6];
    const float* bk = (const float*)d_in[7];
    const float* wv = (const float*)d_in[8];
    const float* bv = (const float*)d_in[9];
    const float* wo = (const float*)d_in[10];
    const float* bo = (const float*)d_in[11];

    float* out    = (float*)d_out;
    float* attn_w = out + (size_t)Bb * Ss * Dd;

    unsigned *Xq, *Xkv, *Wq, *Wk, *Wv, *Wo, *Qp, *Kp, *Vp, *Pp;
    cudaGetSymbolAddress((void**)&Xq,  g_Xq);
    cudaGetSymbolAddress((void**)&Xkv, g_Xkv);
    cudaGetSymbolAddress((void**)&Wq,  g_Wq);
    cudaGetSymbolAddress((void**)&Wk,  g_Wk);
    cudaGetSymbolAddress((void**)&Wv,  g_Wv);
    cudaGetSymbolAddress((void**)&Wo,  g_Wo);
    cudaGetSymbolAddress((void**)&Qp,  g_Qp);
    cudaGetSymbolAddress((void**)&Kp,  g_Kp);
    cudaGetSymbolAddress((void**)&Vp,  g_Vp);
    cudaGetSymbolAddress((void**)&Pp,  g_Pp);

    cudaFuncSetAttribute(gemm_bf3<1>,
        cudaFuncAttributeMaxDynamicSharedMemorySize, GEMM_SMEM);
    cudaFuncSetAttribute(gemm_bf3<0>,
        cudaFuncAttributeMaxDynamicSharedMemorySize, GEMM_SMEM);
    cudaFuncSetAttribute(attn_logits,
        cudaFuncAttributeMaxDynamicSharedMemorySize, ALOG_SMEM);

    detect_bool_mode<<<1, 1>>>((const unsigned int*)mask);

    pack_arr<<<2048, 256>>>(x_q,  Xq,  TOKENS * Dd);
    pack_arr<<<2048, 256>>>(x_kv, Xkv, TOKENS * Dd);
    pack_wT<<<dim3(32, 32), 256>>>(wq, Wq, Dd, Dd);
    pack_wT<<<dim3(32, 32), 256>>>(wk, Wk, Dd, Dd);
    pack_wT<<<dim3(32, 32), 256>>>(wv, Wv, Dd, Dd);
    pack_wT<<<dim3(32, 32), 256>>>(wo, Wo, Dd, Dd);

    const dim3 gg(Dd / 128, TOKENS / 128);   // (8, 32)
    gemm_bf3<1><<<gg, 256, GEMM_SMEM>>>(Xq,  Wq, bq, 0.125f, Qp, nullptr,
                                        TOKENS, Dd, Dd);
    gemm_bf3<1><<<gg, 256, GEMM_SMEM>>>(Xkv, Wk, bk, 1.0f,   Kp, nullptr,
                                        TOKENS, Dd, Dd);
    gemm_bf3<1><<<gg, 256, GEMM_SMEM>>>(Xkv, Wv, bv, 1.0f,   Vp, nullptr,
                                        TOKENS, Dd, Dd);

    attn_logits<<<dim3(Hh, 256, Bb), 256, ALOG_SMEM>>>(mask, drop, attn_w);
    softmax_rows<<<(Bb * Hh * Ss) / 8, 256>>>(attn_w);
    attn_pv<<<dim3(Hh, Ss / 128, Bb), 256>>>(attn_w);

    gemm_bf3<0><<<gg, 256, GEMM_SMEM>>>(Pp, Wo, bo, 1.0f, nullptr, out,
                                        TOKENS, Dd, Dd);
}